// round 1
// baseline (speedup 1.0000x reference)
#include <cuda_runtime.h>
#include <math.h>

#define NB   64
#define CCH  64
#define TT   300
#define VV   25
#define ICH  16
#define OCH  64
#define KTAP 9
#define TV   (TT*VV)        /* 7500 */
#define CTV  (CCH*TV)       /* 480000 */
#define NCTV (NB*CTV)       /* 30720000 */
#define BNEPS 1e-5f

// ---------------- scratch (device globals; no allocation) ----------------
__device__ float g_fab[3*NB*32*TV];        // fa(16)+fb(16) per k,n : 46.08M floats
__device__ float g_S[3*NB*VV*VV];          // attention matrices
__device__ float g_M[3*NB*OCH*TV];         // M = Wd[k] @ x : 92.16M floats
__device__ float g_y1[NB*OCH*TV];          // gcn pre-BN
__device__ float g_y2[NB*OCH*TV];          // after BN1 + res + relu
__device__ float g_y3[NB*OCH*TV];          // after temporal conv
__device__ float g_part[OCH*NB*2];         // BN partial sums
__device__ float g_stat[2*OCH*2];          // [which][o][{scale,shift}]

// ---------------- 1x1 conv producing fa (ch 0..15) and fb (ch 16..31) ----
__global__ __launch_bounds__(256) void k_conv_fab(
    const float* __restrict__ x, const float* __restrict__ Wa,
    const float* __restrict__ ba, const float* __restrict__ Wb,
    const float* __restrict__ bb)
{
    int k = blockIdx.z, n = blockIdx.y;
    int pos = blockIdx.x * 256 + threadIdx.x;
    __shared__ float ws[32*64];
    __shared__ float bs[32];
    for (int i = threadIdx.x; i < 2048; i += 256) {
        int j = i >> 6, c = i & 63;
        ws[i] = (j < 16) ? Wa[(k*16 + j)*64 + c] : Wb[(k*16 + (j-16))*64 + c];
    }
    if (threadIdx.x < 32) {
        int j = threadIdx.x;
        bs[j] = (j < 16) ? ba[k*16 + j] : bb[k*16 + j - 16];
    }
    __syncthreads();
    if (pos >= TV) return;
    float acc[32];
#pragma unroll
    for (int j = 0; j < 32; j++) acc[j] = bs[j];
    const float* xp = x + n*CTV + pos;
    for (int c = 0; c < 64; c++) {
        float xv = xp[c*TV];
#pragma unroll
        for (int j = 0; j < 32; j++) acc[j] += ws[j*64 + c] * xv;
    }
    float* op = g_fab + (k*NB + n)*32*TV + pos;
#pragma unroll
    for (int j = 0; j < 32; j++) op[j*TV] = acc[j];
}

// ---------------- 1x1 conv producing M[k] = Wd[k] @ x (no bias) ----------
__global__ __launch_bounds__(256) void k_conv_M(
    const float* __restrict__ x, const float* __restrict__ Wd)
{
    int k = blockIdx.z, n = blockIdx.y;
    int pos = blockIdx.x * 256 + threadIdx.x;
    __shared__ float ws[64*64];
    for (int i = threadIdx.x; i < 4096; i += 256) ws[i] = Wd[k*4096 + i];
    __syncthreads();
    if (pos >= TV) return;
    float acc[64];
#pragma unroll
    for (int j = 0; j < 64; j++) acc[j] = 0.f;
    const float* xp = x + n*CTV + pos;
    for (int c = 0; c < 64; c++) {
        float xv = xp[c*TV];
#pragma unroll
        for (int j = 0; j < 64; j++) acc[j] += ws[j*64 + c] * xv;
    }
    float* op = g_M + ((k*NB + n)*64)*TV + pos;
#pragma unroll
    for (int j = 0; j < 64; j++) op[j*TV] = acc[j];
}

// ---------------- per-(k,n) 25x25 Gram over IC*T, fused softmax + A ------
__global__ __launch_bounds__(640) void k_gram_softmax(
    const float* __restrict__ adj, const float* __restrict__ PA)
{
    int n = blockIdx.x, k = blockIdx.y;
    int tid = threadIdx.x;
    __shared__ float fas[50*25], fbs[50*25];
    __shared__ float Ss[625];
    const float* fa = g_fab + (k*NB + n)*32*TV;
    const float* fb = fa + 16*TV;
    int v = tid / 25, w = tid % 25;   // valid when tid < 625
    float acc = 0.f;
    for (int o = 0; o < 16; o++) {
        for (int t0 = 0; t0 < TT; t0 += 50) {
            for (int i = tid; i < 1250; i += 640) {
                fas[i] = fa[o*TV + t0*25 + i];
                fbs[i] = fb[o*TV + t0*25 + i];
            }
            __syncthreads();
            if (tid < 625) {
#pragma unroll 10
                for (int tt = 0; tt < 50; tt++)
                    acc += fas[tt*25 + v] * fbs[tt*25 + w];
            }
            __syncthreads();
        }
    }
    if (tid < 625) Ss[tid] = acc * (1.f / 4800.f);
    __syncthreads();
    if (tid < 25) {
        int ww = tid;
        float m = -1e30f;
        for (int vv = 0; vv < 25; vv++) m = fmaxf(m, Ss[vv*25 + ww]);
        float s = 0.f;
        for (int vv = 0; vv < 25; vv++) s += expf(Ss[vv*25 + ww] - m);
        float inv = 1.f / s;
        float* Sp = g_S + (k*NB + n)*625;
        for (int vv = 0; vv < 25; vv++)
            Sp[vv*25 + ww] = expf(Ss[vv*25 + ww] - m)*inv
                           + adj[k*625 + vv*25 + ww] + PA[k*625 + vv*25 + ww];
    }
}

// ---------------- y1[n,o,t,w] = sum_k sum_v M[k,n,o,t,v]*S[k,n,v,w] + bd --
__global__ __launch_bounds__(256) void k_combine(const float* __restrict__ bd)
{
    int tc = blockIdx.x, o = blockIdx.y, n = blockIdx.z;
    int t0 = tc * 60;                       // 5 chunks of 60 t (=1500 pos)
    __shared__ float Ms[3*1500];
    __shared__ float Ssh[3*625];
    for (int i = threadIdx.x; i < 1875; i += 256) {
        int kk = i / 625, r = i % 625;
        Ssh[i] = g_S[(kk*NB + n)*625 + r];
    }
    for (int kk = 0; kk < 3; kk++)
        for (int i = threadIdx.x; i < 1500; i += 256)
            Ms[kk*1500 + i] = g_M[((kk*NB + n)*64 + o)*TV + t0*25 + i];
    __syncthreads();
    float bds = bd[o] + bd[64 + o] + bd[128 + o];
    float* yp = g_y1 + (n*64 + o)*TV + t0*25;
    for (int p = threadIdx.x; p < 1500; p += 256) {
        int tl = p / 25, w = p % 25;
        float acc = bds;
#pragma unroll
        for (int kk = 0; kk < 3; kk++) {
            const float* mrow = Ms + kk*1500 + tl*25;
            const float* srow = Ssh + kk*625 + w;
#pragma unroll
            for (int vv = 0; vv < 25; vv++) acc += mrow[vv] * srow[vv*25];
        }
        yp[p] = acc;
    }
}

// ---------------- BN: deterministic two-stage reduction ------------------
__global__ __launch_bounds__(256) void k_bn_part(int src)
{
    int n = blockIdx.x, o = blockIdx.y;
    const float* y = (src ? g_y3 : g_y1) + (n*64 + o)*TV;
    float s = 0.f, s2 = 0.f;
    for (int i = threadIdx.x; i < TV; i += 256) { float u = y[i]; s += u; s2 += u*u; }
    __shared__ float sh[512];
    sh[threadIdx.x] = s; sh[256 + threadIdx.x] = s2;
    __syncthreads();
    for (int st = 128; st > 0; st >>= 1) {
        if (threadIdx.x < st) {
            sh[threadIdx.x]       += sh[threadIdx.x + st];
            sh[256 + threadIdx.x] += sh[256 + threadIdx.x + st];
        }
        __syncthreads();
    }
    if (threadIdx.x == 0) {
        g_part[(o*NB + n)*2 + 0] = sh[0];
        g_part[(o*NB + n)*2 + 1] = sh[256];
    }
}

__global__ void k_bn_final(const float* __restrict__ g, const float* __restrict__ b, int which)
{
    int o = threadIdx.x;   // 64 threads
    float s = 0.f, s2 = 0.f;
    for (int n = 0; n < NB; n++) {
        s  += g_part[(o*NB + n)*2 + 0];
        s2 += g_part[(o*NB + n)*2 + 1];
    }
    const float cnt = (float)(NB*TV);
    float mean = s / cnt;
    float var  = s2 / cnt - mean*mean;
    float sc = g[o] * rsqrtf(var + BNEPS);
    g_stat[which*128 + o*2 + 0] = sc;
    g_stat[which*128 + o*2 + 1] = b[o] - mean*sc;
}

// which==0: y2 = relu(bn1(y1)+x)   which==1: out = relu(bn2(y3)+x)
__global__ __launch_bounds__(256) void k_bn_apply(
    const float* __restrict__ x, float* __restrict__ outExt, int which)
{
    const float* yin = which ? g_y3 : g_y1;
    float* out = which ? outExt : g_y2;
    for (long i = (long)blockIdx.x*256 + threadIdx.x; i < NCTV; i += (long)gridDim.x*256) {
        int o = (int)((i / TV) & 63);
        float sc = g_stat[which*128 + o*2 + 0];
        float sf = g_stat[which*128 + o*2 + 1];
        out[i] = fmaxf(0.f, yin[i]*sc + sf + x[i]);
    }
}

// ---------------- temporal conv: y3 = Wt (*) y2 + bt ----------------------
__global__ __launch_bounds__(256) void k_tcn(
    const float* __restrict__ Wt, const float* __restrict__ bt)
{
    int tb = blockIdx.x, n = blockIdx.y;
    int t0 = tb * 10;
    __shared__ float ys[8*18*25];    // 3600 floats (8 in-ch, 18 t, 25 v)
    __shared__ float ws[64*8*9];     // 4608 floats
    int tid = threadIdx.x;
    float acc[64];
#pragma unroll
    for (int o = 0; o < 64; o++) acc[o] = 0.f;
    int tl = tid / 25, v = tid % 25;   // valid for tid < 250
    for (int ci = 0; ci < 8; ci++) {
        for (int i = tid; i < 4608; i += 256) {
            int o = i / 72, r = i % 72;
            int il = r / 9, kt = r % 9;
            ws[i] = Wt[o*576 + (ci*8 + il)*9 + kt];
        }
        for (int i = tid; i < 3600; i += 256) {
            int il = i / 450, r = i % 450;
            int tt = r / 25, vv = r % 25;
            int tg = t0 + tt - 4;
            ys[i] = (tg >= 0 && tg < TT) ? g_y2[(n*64 + ci*8 + il)*TV + tg*25 + vv] : 0.f;
        }
        __syncthreads();
        if (tid < 250) {
            for (int il = 0; il < 8; il++) {
#pragma unroll
                for (int kt = 0; kt < KTAP; kt++) {
                    float yv = ys[il*450 + (tl + kt)*25 + v];
                    const float* wp = ws + il*9 + kt;
#pragma unroll
                    for (int o = 0; o < 64; o++) acc[o] += wp[o*72] * yv;
                }
            }
        }
        __syncthreads();
    }
    if (tid < 250) {
        float* yp = g_y3 + (n*64)*TV + (t0 + tl)*25 + v;
#pragma unroll
        for (int o = 0; o < 64; o++) yp[o*TV] = acc[o] + bt[o];
    }
}

// ---------------- launch --------------------------------------------------
extern "C" void kernel_launch(void* const* d_in, const int* in_sizes, int n_in,
                              void* d_out, int out_size)
{
    const float* x    = (const float*)d_in[0];
    const float* adj  = (const float*)d_in[1];
    const float* PA   = (const float*)d_in[2];
    const float* Wa   = (const float*)d_in[3];
    const float* ba   = (const float*)d_in[4];
    const float* Wb   = (const float*)d_in[5];
    const float* bb   = (const float*)d_in[6];
    const float* Wd   = (const float*)d_in[7];
    const float* bd   = (const float*)d_in[8];
    const float* g1   = (const float*)d_in[9];
    const float* b1   = (const float*)d_in[10];
    const float* Wt   = (const float*)d_in[11];
    const float* bt   = (const float*)d_in[12];
    const float* g2   = (const float*)d_in[13];
    const float* b2   = (const float*)d_in[14];
    float* out = (float*)d_out;

    dim3 gconv(30, NB, 3);
    k_conv_fab<<<gconv, 256>>>(x, Wa, ba, Wb, bb);
    k_conv_M<<<gconv, 256>>>(x, Wd);
    k_gram_softmax<<<dim3(NB, 3), 640>>>(adj, PA);
    k_combine<<<dim3(5, OCH, NB), 256>>>(bd);

    k_bn_part<<<dim3(NB, OCH), 256>>>(0);
    k_bn_final<<<1, 64>>>(g1, b1, 0);
    k_bn_apply<<<8192, 256>>>(x, out, 0);       // -> g_y2

    k_tcn<<<dim3(30, NB), 256>>>(Wt, bt);       // -> g_y3

    k_bn_part<<<dim3(NB, OCH), 256>>>(1);
    k_bn_final<<<1, 64>>>(g2, b2, 1);
    k_bn_apply<<<8192, 256>>>(x, out, 1);       // -> d_out

    // second tuple element: adj_mat passthrough
    long tail = (long)out_size - (long)NCTV;
    if (tail > 0) {
        long cnt = tail < 1875 ? tail : 1875;
        cudaMemcpyAsync(out + NCTV, d_in[1], cnt * sizeof(float),
                        cudaMemcpyDeviceToDevice);
    }
}

// round 2
// speedup vs baseline: 1.8443x; 1.8443x over previous
#include <cuda_runtime.h>
#include <math.h>

#define NB   64
#define CCH  64
#define TT   300
#define VV   25
#define ICH  16
#define OCH  64
#define KTAP 9
#define TV   (TT*VV)        /* 7500 */
#define CTV  (CCH*TV)       /* 480000 */
#define NCTV (NB*CTV)       /* 30720000 */
#define BNEPS 1e-5f

// ---------------- scratch (device globals; no allocation) ----------------
__device__ float g_fab[3*NB*32*TV];        // fa(16)+fb(16) per k,n
__device__ float g_S[3*NB*VV*VV];          // attention matrices
__device__ float g_M[3*NB*OCH*TV];         // M = Wd[k] @ x
__device__ float g_y1[NB*OCH*TV];          // gcn pre-BN
__device__ float g_y3t[NB*OCH*TV];         // tcn output, [n][o][v][t] layout
__device__ float g_WtT[OCH*OCH*KTAP];      // Wt transposed: [(ic*9+kt)*64+o]
__device__ float g_pA_s[OCH*256];          // BN1 partials (sum)
__device__ float g_pA_q[OCH*256];          // BN1 partials (sumsq)
__device__ float g_pB_s[OCH*4800];         // BN2 partials
__device__ float g_pB_q[OCH*4800];
__device__ float g_stat[2*OCH*2];          // [which][o][{scale,shift}]

// ---------------- Wt transpose: [o][ic][kt] -> [(ic*9+kt)*64+o] ----------
__global__ void k_transpose_wt(const float* __restrict__ Wt)
{
    int j = blockIdx.x*256 + threadIdx.x;
    if (j >= OCH*OCH*KTAP) return;
    int o = j & 63;
    int r = j >> 6;            // ic*9+kt
    int ic = r / 9, kt = r % 9;
    g_WtT[j] = Wt[(o*64 + ic)*9 + kt];
}

// ---------------- 1x1 conv producing fa (ch 0..15) and fb (16..31) -------
__global__ __launch_bounds__(256) void k_conv_fab(
    const float* __restrict__ x, const float* __restrict__ Wa,
    const float* __restrict__ ba, const float* __restrict__ Wb,
    const float* __restrict__ bb)
{
    int k = blockIdx.z, n = blockIdx.y;
    int pos = blockIdx.x * 256 + threadIdx.x;
    __shared__ float ws[64*36];          // transposed [c][j], pad 36
    __shared__ float bs[32];
    for (int i = threadIdx.x; i < 2048; i += 256) {
        int j = i >> 6, c = i & 63;
        float w = (j < 16) ? Wa[(k*16 + j)*64 + c] : Wb[(k*16 + (j-16))*64 + c];
        ws[c*36 + j] = w;
    }
    if (threadIdx.x < 32) {
        int j = threadIdx.x;
        bs[j] = (j < 16) ? ba[k*16 + j] : bb[k*16 + j - 16];
    }
    __syncthreads();
    if (pos >= TV) return;
    float acc[32];
#pragma unroll
    for (int j = 0; j < 32; j++) acc[j] = bs[j];
    const float* xp = x + n*CTV + pos;
    for (int c = 0; c < 64; c++) {
        float xv = xp[c*TV];
        const float4* wr = (const float4*)(ws + c*36);
#pragma unroll
        for (int j4 = 0; j4 < 8; j4++) {
            float4 w = wr[j4];
            acc[j4*4+0] += w.x * xv;
            acc[j4*4+1] += w.y * xv;
            acc[j4*4+2] += w.z * xv;
            acc[j4*4+3] += w.w * xv;
        }
    }
    float* op = g_fab + (k*NB + n)*32*TV + pos;
#pragma unroll
    for (int j = 0; j < 32; j++) op[j*TV] = acc[j];
}

// ---------------- 1x1 conv producing M[k] = Wd[k] @ x ---------------------
__global__ __launch_bounds__(256) void k_conv_M(
    const float* __restrict__ x, const float* __restrict__ Wd)
{
    int k = blockIdx.z, n = blockIdx.y;
    int pos = blockIdx.x * 256 + threadIdx.x;
    __shared__ float ws[64*68];          // transposed [c][j], pad 68
    for (int i = threadIdx.x; i < 4096; i += 256) {
        int j = i >> 6, c = i & 63;
        ws[c*68 + j] = Wd[k*4096 + i];
    }
    __syncthreads();
    if (pos >= TV) return;
    float acc[64];
#pragma unroll
    for (int j = 0; j < 64; j++) acc[j] = 0.f;
    const float* xp = x + n*CTV + pos;
    for (int c = 0; c < 64; c++) {
        float xv = xp[c*TV];
        const float4* wr = (const float4*)(ws + c*68);
#pragma unroll
        for (int j4 = 0; j4 < 16; j4++) {
            float4 w = wr[j4];
            acc[j4*4+0] += w.x * xv;
            acc[j4*4+1] += w.y * xv;
            acc[j4*4+2] += w.z * xv;
            acc[j4*4+3] += w.w * xv;
        }
    }
    float* op = g_M + ((k*NB + n)*64)*TV + pos;
#pragma unroll
    for (int j = 0; j < 64; j++) op[j*TV] = acc[j];
}

// ---------------- per-(k,n) 25x25 Gram over IC*T, fused softmax + A ------
__global__ __launch_bounds__(640) void k_gram_softmax(
    const float* __restrict__ adj, const float* __restrict__ PA)
{
    int n = blockIdx.x, k = blockIdx.y;
    int tid = threadIdx.x;
    __shared__ float fas[50*25], fbs[50*25];
    __shared__ float Ss[625];
    const float* fa = g_fab + (k*NB + n)*32*TV;
    const float* fb = fa + 16*TV;
    int v = tid / 25, w = tid % 25;
    float acc = 0.f;
    for (int o = 0; o < 16; o++) {
        for (int t0 = 0; t0 < TT; t0 += 50) {
            for (int i = tid; i < 1250; i += 640) {
                fas[i] = fa[o*TV + t0*25 + i];
                fbs[i] = fb[o*TV + t0*25 + i];
            }
            __syncthreads();
            if (tid < 625) {
#pragma unroll 10
                for (int tt = 0; tt < 50; tt++)
                    acc += fas[tt*25 + v] * fbs[tt*25 + w];
            }
            __syncthreads();
        }
    }
    if (tid < 625) Ss[tid] = acc * (1.f / 4800.f);
    __syncthreads();
    if (tid < 25) {
        int ww = tid;
        float m = -1e30f;
        for (int vv = 0; vv < 25; vv++) m = fmaxf(m, Ss[vv*25 + ww]);
        float s = 0.f;
        for (int vv = 0; vv < 25; vv++) s += expf(Ss[vv*25 + ww] - m);
        float inv = 1.f / s;
        float* Sp = g_S + (k*NB + n)*625;
        for (int vv = 0; vv < 25; vv++)
            Sp[vv*25 + ww] = expf(Ss[vv*25 + ww] - m)*inv
                           + adj[k*625 + vv*25 + ww] + PA[k*625 + vv*25 + ww];
    }
}

// ---- y1[n,o,t,w] = sum_k sum_v M[k,n,o,t,v]*S[k,n,v,w] + bd (+BN1 part) --
__global__ __launch_bounds__(128) void k_combine(const float* __restrict__ bd)
{
    int tc = blockIdx.x, o = blockIdx.y, n = blockIdx.z;
    int t0 = tc * 75;
    __shared__ float Ms[3*1875];
    __shared__ float Ssh[3*625];
    __shared__ float red[256];
    int tid = threadIdx.x;
    for (int i = tid; i < 1875; i += 128) {
        int kk = i / 625, r = i % 625;
        Ssh[i] = g_S[(kk*NB + n)*625 + r];
    }
#pragma unroll
    for (int kk = 0; kk < 3; kk++)
        for (int i = tid; i < 1875; i += 128)
            Ms[kk*1875 + i] = g_M[((kk*NB + n)*64 + o)*TV + t0*25 + i];
    __syncthreads();
    float bds = bd[o] + bd[64 + o] + bd[128 + o];
    float acc[3][5];
    int wq = tid % 5, tq = tid / 5;        // tq 0..24 valid when tid<125
    int tb = tq * 3, wb = wq * 5;
    bool act = tid < 125;
#pragma unroll
    for (int i = 0; i < 3; i++)
#pragma unroll
        for (int j = 0; j < 5; j++) acc[i][j] = bds;
    if (act) {
#pragma unroll
        for (int kk = 0; kk < 3; kk++) {
            const float* Mb = Ms + kk*1875;
            const float* Sb = Ssh + kk*625;
            for (int vv = 0; vv < 25; vv++) {
                float m0 = Mb[(tb+0)*25 + vv];
                float m1 = Mb[(tb+1)*25 + vv];
                float m2 = Mb[(tb+2)*25 + vv];
                const float* sr = Sb + vv*25 + wb;
#pragma unroll
                for (int j = 0; j < 5; j++) {
                    float sv = sr[j];
                    acc[0][j] += m0 * sv;
                    acc[1][j] += m1 * sv;
                    acc[2][j] += m2 * sv;
                }
            }
        }
    }
    __syncthreads();           // Ms fully consumed
    if (act) {
#pragma unroll
        for (int i = 0; i < 3; i++)
#pragma unroll
            for (int j = 0; j < 5; j++)
                Ms[(tb+i)*25 + wb + j] = acc[i][j];
    }
    __syncthreads();
    // coalesced store + BN1 partials
    float s = 0.f, s2 = 0.f;
    float* yp = g_y1 + (n*64 + o)*TV + t0*25;
    for (int i = tid; i < 1875; i += 128) {
        float u = Ms[i];
        yp[i] = u;
        s += u; s2 += u*u;
    }
    red[tid] = s; red[128 + tid] = s2;
    __syncthreads();
    for (int st = 64; st > 0; st >>= 1) {
        if (tid < st) {
            red[tid]       += red[tid + st];
            red[128 + tid] += red[128 + tid + st];
        }
        __syncthreads();
    }
    if (tid == 0) {
        g_pA_s[o*256 + n*4 + tc] = red[0];
        g_pA_q[o*256 + n*4 + tc] = red[128];
    }
}

// ---------------- BN finalize from partials -------------------------------
__global__ void k_bn_final(const float* __restrict__ g, const float* __restrict__ b,
                           const float* __restrict__ ps, const float* __restrict__ pq,
                           int npart, int which)
{
    int o = blockIdx.x;
    int tid = threadIdx.x;
    __shared__ float red[256];
    float s = 0.f, s2 = 0.f;
    for (int i = tid; i < npart; i += 128) {
        s  += ps[o*npart + i];
        s2 += pq[o*npart + i];
    }
    red[tid] = s; red[128 + tid] = s2;
    __syncthreads();
    for (int st = 64; st > 0; st >>= 1) {
        if (tid < st) {
            red[tid]       += red[tid + st];
            red[128 + tid] += red[128 + tid + st];
        }
        __syncthreads();
    }
    if (tid == 0) {
        const float cnt = (float)(NB*TV);
        float mean = red[0] / cnt;
        float var  = red[128] / cnt - mean*mean;
        float sc = g[o] * rsqrtf(var + BNEPS);
        g_stat[which*128 + o*2 + 0] = sc;
        g_stat[which*128 + o*2 + 1] = b[o] - mean*sc;
    }
}

// ---- tcn: y3t = Wt (*) relu(bn1(y1)+x) + bt ; transposed out + BN2 part --
// grid (vc=5, tcb=15, n=64) block 320 = 64 o x 5 vs
__global__ __launch_bounds__(320, 2) void k_tcn2(
    const float* __restrict__ x, const float* __restrict__ bt)
{
    __shared__ float wsm[4*9*64];     // 2304
    __shared__ float ysm[4*28*5];     // 560
    __shared__ float red[640];
    int tid = threadIdx.x;
    int o  = tid & 63;
    int vs = tid >> 6;                 // 0..4
    int vcb = blockIdx.x, tcb = blockIdx.y, n = blockIdx.z;
    int t0 = tcb * 20;
    int v  = vcb * 5 + vs;             // always < 25
    float acc[20];
#pragma unroll
    for (int t = 0; t < 20; t++) acc[t] = 0.f;

    for (int ch = 0; ch < 16; ch++) {
        // weights chunk [il][kt][o]
        for (int i = tid; i < 2304; i += 320)
            wsm[i] = g_WtT[ch*2304 + i];
        // y tile with fused BN1 apply + residual + relu
        for (int i = tid; i < 560; i += 320) {
            int il = i / 140, r = i % 140;
            int tt = r / 5, vv = r % 5;
            int tg = t0 + tt - 4;
            int cin = ch*4 + il;
            float val = 0.f;
            if (tg >= 0 && tg < TT) {
                int idx = (n*64 + cin)*TV + tg*25 + vcb*5 + vv;
                float sc = g_stat[cin*2 + 0];
                float sf = g_stat[cin*2 + 1];
                val = fmaxf(0.f, g_y1[idx]*sc + sf + x[idx]);
            }
            ysm[(il*28 + tt)*5 + vv] = val;
        }
        __syncthreads();
        float w[4][9];
#pragma unroll
        for (int il = 0; il < 4; il++)
#pragma unroll
            for (int kt = 0; kt < 9; kt++)
                w[il][kt] = wsm[(il*9 + kt)*64 + o];
#pragma unroll
        for (int il = 0; il < 4; il++) {
#pragma unroll
            for (int tt = 0; tt < 28; tt++) {
                float yv = ysm[(il*28 + tt)*5 + vs];
#pragma unroll
                for (int kt = 0; kt < 9; kt++) {
                    int tl = tt - kt;
                    if (tl >= 0 && tl < 20)
                        acc[tl] += w[il][kt] * yv;
                }
            }
        }
        __syncthreads();
    }
    // epilogue: bias, partials, transposed store (t-contiguous)
    float bv = bt[o];
    float s = 0.f, s2 = 0.f;
#pragma unroll
    for (int t = 0; t < 20; t++) {
        acc[t] += bv;
        s += acc[t]; s2 += acc[t]*acc[t];
    }
    float* yp = g_y3t + (n*64 + o)*TV + v*TT + t0;
#pragma unroll
    for (int t4 = 0; t4 < 5; t4++) {
        float4 st4 = make_float4(acc[t4*4+0], acc[t4*4+1], acc[t4*4+2], acc[t4*4+3]);
        *(float4*)(yp + t4*4) = st4;
    }
    red[tid] = s; red[320 + tid] = s2;
    __syncthreads();
    if (tid < 64) {
        float ss = 0.f, qq = 0.f;
#pragma unroll
        for (int k = 0; k < 5; k++) {
            ss += red[tid + 64*k];
            qq += red[320 + tid + 64*k];
        }
        int p = (n*15 + tcb)*5 + vcb;
        g_pB_s[tid*4800 + p] = ss;
        g_pB_q[tid*4800 + p] = qq;
    }
}

// ---- final: out = relu(bn2(y3t) + x), reading transposed y3 -------------
__global__ __launch_bounds__(256) void k_bn_apply_t(
    const float* __restrict__ x, float* __restrict__ out)
{
    __shared__ float sm[25*301];
    int n = blockIdx.x, o = blockIdx.y;
    int tid = threadIdx.x;
    int base = (n*64 + o)*TV;
    for (int i = tid; i < TV; i += 256) {
        int v = i / 300, t = i % 300;
        sm[v*301 + t] = g_y3t[base + i];
    }
    __syncthreads();
    float sc = g_stat[128 + o*2 + 0];
    float sf = g_stat[128 + o*2 + 1];
    for (int i = tid; i < TV; i += 256) {
        int t = i / 25, v = i % 25;
        out[base + i] = fmaxf(0.f, sm[v*301 + t]*sc + sf + x[base + i]);
    }
}

// ---------------- launch --------------------------------------------------
extern "C" void kernel_launch(void* const* d_in, const int* in_sizes, int n_in,
                              void* d_out, int out_size)
{
    const float* x    = (const float*)d_in[0];
    const float* adj  = (const float*)d_in[1];
    const float* PA   = (const float*)d_in[2];
    const float* Wa   = (const float*)d_in[3];
    const float* ba   = (const float*)d_in[4];
    const float* Wb   = (const float*)d_in[5];
    const float* bb   = (const float*)d_in[6];
    const float* Wd   = (const float*)d_in[7];
    const float* bd   = (const float*)d_in[8];
    const float* g1   = (const float*)d_in[9];
    const float* b1   = (const float*)d_in[10];
    const float* Wt   = (const float*)d_in[11];
    const float* bt   = (const float*)d_in[12];
    const float* g2   = (const float*)d_in[13];
    const float* b2   = (const float*)d_in[14];
    float* out = (float*)d_out;

    float *pAs, *pAq, *pBs, *pBq;
    cudaGetSymbolAddress((void**)&pAs, g_pA_s);
    cudaGetSymbolAddress((void**)&pAq, g_pA_q);
    cudaGetSymbolAddress((void**)&pBs, g_pB_s);
    cudaGetSymbolAddress((void**)&pBq, g_pB_q);

    k_transpose_wt<<<144, 256>>>(Wt);

    dim3 gconv(30, NB, 3);
    k_conv_fab<<<gconv, 256>>>(x, Wa, ba, Wb, bb);
    k_conv_M<<<gconv, 256>>>(x, Wd);
    k_gram_softmax<<<dim3(NB, 3), 640>>>(adj, PA);
    k_combine<<<dim3(4, OCH, NB), 128>>>(bd);

    k_bn_final<<<64, 128>>>(g1, b1, pAs, pAq, 256, 0);

    k_tcn2<<<dim3(5, 15, NB), 320>>>(x, bt);

    k_bn_final<<<64, 128>>>(g2, b2, pBs, pBq, 4800, 1);

    k_bn_apply_t<<<dim3(NB, OCH), 256>>>(x, out);

    // second tuple element: adj_mat passthrough
    long tail = (long)out_size - (long)NCTV;
    if (tail > 0) {
        long cnt = tail < 1875 ? tail : 1875;
        cudaMemcpyAsync(out + NCTV, d_in[1], cnt * sizeof(float),
                        cudaMemcpyDeviceToDevice);
    }
}